// round 10
// baseline (speedup 1.0000x reference)
#include <cuda_runtime.h>
#include <stdint.h>

#define BSZ   1024
#define NDIM  1024
#define TLEN  100

// d_out layout (float elements)
#define OFF_ACT 0
#define OFF_E3H 2048
#define OFF_E5H (2048 + 102400)
#define OFF_C1H (2048 + 2*102400)
#define OFF_EC3 (2048 + 3*102400)
#define OFF_EC5 (OFF_EC3 + 1048576)
#define OFF_CA1 (OFF_EC5 + 1048576)

__device__ float    g_drive[TLEN * NDIM];
__device__ uint32_t g_keys[2 * TLEN];
__device__ float    g_wt1[NDIM * NDIM];   // wec3ca1^T [n][k], tf32-rounded
__device__ float    g_wt2[NDIM * NDIM];   // wca1ec5^T [n][k], tf32-rounded
__device__ float    g_at1[NDIM * NDIM];   // tf32-rounded ec3 (A of step1)
__device__ float    g_at2[NDIM * NDIM];   // tf32-rounded ca1 (A of step2)

// GEMM tiling: block 128(M) x 64(N), K-tile 64 (16 iterations), 8 warps 4(m)x2(n),
// warp tile 32x32. cp.async 3-stage; ldmatrix.x4 fragments, kk double-buffered.
#define KTILE  64
#define KTILES 16
#define PITCH  68                                // 64 + 4 pad
#define STAGE_A_BYTES (128 * PITCH * 4)          // 34816
#define STAGE_BYTES   (192 * PITCH * 4)          // 52224
#define NSTAGE 3
#define SMEM_DYN (NSTAGE * STAGE_BYTES)          // 156672

// ---------------------------------------------------------------------------
__device__ __forceinline__ float tf32r(float x) {
    uint32_t u = __float_as_uint(x);
    asm("cvt.rna.tf32.f32 %0, %0;" : "+r"(u));
    return __uint_as_float(u);
}
__device__ __forceinline__ float sigmoidf(float x) { return 1.0f / (1.0f + expf(-x)); }
__device__ __forceinline__ uint32_t smem_to_u32(const void* p) {
    uint32_t a;
    asm("{ .reg .u64 t; cvta.to.shared.u64 t, %1; cvt.u32.u64 %0, t; }" : "=r"(a) : "l"(p));
    return a;
}
__device__ __forceinline__ void cp16(uint32_t dst, const void* src) {
    asm volatile("cp.async.cg.shared.global [%0], [%1], 16;" :: "r"(dst), "l"(src));
}
__device__ __forceinline__ void cp_commit() { asm volatile("cp.async.commit_group;"); }
__device__ __forceinline__ void ldsm4(uint32_t r[4], uint32_t addr) {
    asm volatile("ldmatrix.sync.aligned.m8n8.x4.shared.b16 {%0,%1,%2,%3}, [%4];"
        : "=r"(r[0]), "=r"(r[1]), "=r"(r[2]), "=r"(r[3]) : "r"(addr));
}
__device__ __forceinline__ void mma8(float c[4], const uint32_t a[4], const uint32_t b[2]) {
    asm volatile(
        "mma.sync.aligned.m16n8k8.row.col.f32.tf32.tf32.f32 "
        "{%0,%1,%2,%3}, {%4,%5,%6,%7}, {%8,%9}, {%0,%1,%2,%3};"
        : "+f"(c[0]), "+f"(c[1]), "+f"(c[2]), "+f"(c[3])
        : "r"(a[0]), "r"(a[1]), "r"(a[2]), "r"(a[3]), "r"(b[0]), "r"(b[1]));
}

// ---------------------------------------------------------------------------
// Threefry-2x32 (jax partitionable) — validated
// ---------------------------------------------------------------------------
__device__ __forceinline__ void threefry2x32(uint32_t k0, uint32_t k1,
                                             uint32_t x0, uint32_t x1,
                                             uint32_t& o0, uint32_t& o1) {
    uint32_t ks2 = k0 ^ k1 ^ 0x1BD11BDAu;
    x0 += k0; x1 += k1;
#define TF_R(r) { x0 += x1; x1 = __funnelshift_l(x1, x1, (r)); x1 ^= x0; }
    TF_R(13) TF_R(15) TF_R(26) TF_R(6)
    x0 += k1;  x1 += ks2 + 1u;
    TF_R(17) TF_R(29) TF_R(16) TF_R(24)
    x0 += ks2; x1 += k0 + 2u;
    TF_R(13) TF_R(15) TF_R(26) TF_R(6)
    x0 += k0;  x1 += k1 + 3u;
    TF_R(17) TF_R(29) TF_R(16) TF_R(24)
    x0 += k1;  x1 += ks2 + 4u;
    TF_R(13) TF_R(15) TF_R(26) TF_R(6)
    x0 += ks2; x1 += k0 + 5u;
#undef TF_R
    o0 = x0; o1 = x1;
}

__device__ __forceinline__ bool noise_hit(uint32_t k0, uint32_t k1, uint32_t idx) {
    uint32_t o0, o1;
    threefry2x32(k0, k1, 0u, idx, o0, o1);
    uint32_t bits = o0 ^ o1;
    float u = __uint_as_float((bits >> 9) | 0x3f800000u) - 1.0f;
    return u < 0.004f;
}

// ---------------------------------------------------------------------------
// prep kernel: everything one-time, in ONE launch (keeps ncu -s 5 on step kernels)
//  blk [0,1024):    transpose+round wec3ca1 -> g_wt1
//  blk [1024,2048): transpose+round wca1ec5 -> g_wt2
//  blk [2048,3072): ec3 init: d_out.ec3 = ec3_last, g_at1 = tf32r(ec3_last)
//  blk [3072,4096): ec5 init: d_out.ec5 = ec5_last
//  blk [4096,4196): drive row t = blk-4096
//  blk 4196:        threefry step keys
// ---------------------------------------------------------------------------
__global__ __launch_bounds__(256) void prep_kernel(
    const float* __restrict__ wec3ca1, const float* __restrict__ wca1ec5,
    const float* __restrict__ ec3_last, const float* __restrict__ ec5_last,
    const float* __restrict__ wca3ca1,
    float* __restrict__ ec3, float* __restrict__ ec5)
{
    __shared__ float tile[32][33];
    __shared__ float ca3[NDIM];
    const int blk = blockIdx.x;
    const int tid = threadIdx.x;

    if (blk < 2048) {                        // transposes
        const float* W = (blk < 1024) ? wec3ca1 : wca1ec5;
        float* dst     = (blk < 1024) ? g_wt1  : g_wt2;
        int b = blk & 1023;
        int bx = (b & 31) * 32, by = (b >> 5) * 32;
        int x = tid & 31, y = tid >> 5;      // 32 x 8
#pragma unroll
        for (int i = 0; i < 32; i += 8)
            tile[y + i][x] = tf32r(W[(size_t)(by + y + i) * NDIM + bx + x]);
        __syncthreads();
#pragma unroll
        for (int i = 0; i < 32; i += 8)
            dst[(size_t)(bx + y + i) * NDIM + by + x] = tile[x][y + i];
    } else if (blk < 3072) {                 // ec3 init + rounded copy
        int i = ((blk - 2048) * 256 + tid) * 4;
        float4 v = *(const float4*)(ec3_last + i);
        *(float4*)(ec3 + i) = v;
        v.x = tf32r(v.x); v.y = tf32r(v.y); v.z = tf32r(v.z); v.w = tf32r(v.w);
        *(float4*)(g_at1 + i) = v;
    } else if (blk < 4096) {                 // ec5 init
        int i = ((blk - 3072) * 256 + tid) * 4;
        *(float4*)(ec5 + i) = *(const float4*)(ec5_last + i);
    } else if (blk < 4196) {                 // drive
        const int t = blk - 4096;
        const float x = (float)t;
        for (int c = tid; c < NDIM; c += 256) {
            float center = (100.0f / 1023.0f) * (float)c;
            float d = center - x;
            ca3[c] = tf32r(expf(-(d * d) / 50.0f));
        }
        __syncthreads();
        for (int n = tid; n < NDIM; n += 256) {
            float acc = 0.0f;
            for (int k = 0; k < NDIM; k++)
                acc += ca3[k] * tf32r(wca3ca1[k * NDIM + n]);
            g_drive[t * NDIM + n] = acc;
        }
    } else {                                 // keys
        if (tid < TLEN) {
            uint32_t o0, o1;
            threefry2x32(0u, 42u, 0u, (uint32_t)tid, o0, o1);
            g_keys[2 * tid] = o0; g_keys[2 * tid + 1] = o1;
        }
    }
}

// ---------------------------------------------------------------------------
// GEMM core: acc[2][4][4] += A(pre-tf32)[128 x 1024] @ Bt(pre-tf32)^T, N-tile 64.
// cp.async 3-stage (issued before mma), kk-double-buffered ldmatrix fragments.
// ---------------------------------------------------------------------------
__device__ __forceinline__ void issue_tile(
    const float* __restrict__ A, const float* __restrict__ Bt,
    int m0, int n0, int kt, int stage, uint32_t sb, int tid)
{
    const int row = tid >> 4, col4 = (tid & 15) * 4;
    const float* ag = A + (size_t)(m0 + row) * NDIM + kt * KTILE + col4;
    uint32_t ad = sb + stage * STAGE_BYTES + (row * PITCH + col4) * 4;
#pragma unroll
    for (int i = 0; i < 8; i++)
        cp16(ad + i * 16 * PITCH * 4, ag + (size_t)i * 16 * NDIM);
    const float* bg = Bt + (size_t)(n0 + row) * NDIM + kt * KTILE + col4;
    uint32_t bd = sb + stage * STAGE_BYTES + STAGE_A_BYTES + (row * PITCH + col4) * 4;
#pragma unroll
    for (int i = 0; i < 4; i++)
        cp16(bd + i * 16 * PITCH * 4, bg + (size_t)i * 16 * NDIM);
    cp_commit();
}

__device__ __forceinline__ void gemm_mma_tf32(
    const float* __restrict__ A, const float* __restrict__ Bt,
    float* sm, float acc[2][4][4])
{
    const int tid  = threadIdx.x;
    const int lane = tid & 31, warp = tid >> 5;
    const int wm = warp & 3, wn = warp >> 2;
    const int m0 = blockIdx.y * 128, n0 = blockIdx.x * 64;
    const uint32_t sb = smem_to_u32(sm);

    const int q = lane >> 3, r = lane & 7;
    uint32_t aoff[2], boff[2];
#pragma unroll
    for (int mi = 0; mi < 2; mi++) {
        int rowA = wm * 32 + mi * 16 + r + ((q & 1) ? 8 : 0);
        int colA = (q & 2) ? 4 : 0;
        aoff[mi] = (uint32_t)((rowA * PITCH + colA) * 4);
    }
#pragma unroll
    for (int j = 0; j < 2; j++) {
        int rowB = wn * 32 + j * 16 + r + ((q & 2) ? 8 : 0);
        int colB = (q & 1) ? 4 : 0;
        boff[j] = (uint32_t)(STAGE_A_BYTES + (rowB * PITCH + colB) * 4);
    }

#pragma unroll
    for (int mi = 0; mi < 2; mi++)
#pragma unroll
        for (int nj = 0; nj < 4; nj++)
#pragma unroll
            for (int c = 0; c < 4; c++) acc[mi][nj][c] = 0.0f;

    issue_tile(A, Bt, m0, n0, 0, 0, sb, tid);
    issue_tile(A, Bt, m0, n0, 1, 1, sb, tid);

    for (int kt = 0; kt < KTILES; kt++) {
        if (kt < KTILES - 2) asm volatile("cp.async.wait_group 1;");
        else                 asm volatile("cp.async.wait_group 0;");
        __syncthreads();
        // overlap next-next tile's loads with this tile's compute
        if (kt + 2 < KTILES)
            issue_tile(A, Bt, m0, n0, kt + 2, (kt + 2) % 3, sb, tid);

        const uint32_t st = sb + (uint32_t)(kt % 3) * STAGE_BYTES;

        // kk-double-buffered fragments
        uint32_t af[2][2][4], b01[2][4], b23[2][4];
        ldsm4(af[0][0], st + aoff[0]);
        ldsm4(af[0][1], st + aoff[1]);
        ldsm4(b01[0],   st + boff[0]);
        ldsm4(b23[0],   st + boff[1]);
#pragma unroll
        for (int kk = 0; kk < 8; kk++) {
            const int cur = kk & 1, nxt = cur ^ 1;
            if (kk < 7) {
                ldsm4(af[nxt][0], st + aoff[0] + (kk + 1) * 32);
                ldsm4(af[nxt][1], st + aoff[1] + (kk + 1) * 32);
                ldsm4(b01[nxt],   st + boff[0] + (kk + 1) * 32);
                ldsm4(b23[nxt],   st + boff[1] + (kk + 1) * 32);
            }
#pragma unroll
            for (int mi = 0; mi < 2; mi++) {
                mma8(acc[mi][0], af[cur][mi], &b01[cur][0]);
                mma8(acc[mi][1], af[cur][mi], &b01[cur][2]);
                mma8(acc[mi][2], af[cur][mi], &b23[cur][0]);
                mma8(acc[mi][3], af[cur][mi], &b23[cur][2]);
            }
        }
    }
}

// ---------------------------------------------------------------------------
// step1: ca1 = relu(drive_t * (1 + sigmoid(ec3 @ wec3ca1)) - ca1bias)
// ---------------------------------------------------------------------------
__global__ __launch_bounds__(256) void step1_mma(
    const float* __restrict__ ca1bias,
    float* __restrict__ ca1, float* __restrict__ c1h, int t, int last)
{
    extern __shared__ float sm[];
    float acc[2][4][4];
    gemm_mma_tf32(g_at1, g_wt1, sm, acc);

    const int lane = threadIdx.x & 31, warp = threadIdx.x >> 5;
    const int group = lane >> 2, tig = lane & 3;
    const int wm = warp & 3, wn = warp >> 2;
    const int m0 = blockIdx.y * 128, n0 = blockIdx.x * 64;
    const float* drive = &g_drive[t * NDIM];

#pragma unroll
    for (int mi = 0; mi < 2; mi++)
#pragma unroll
        for (int nj = 0; nj < 4; nj++)
#pragma unroll
            for (int c = 0; c < 4; c++) {
                const int m = m0 + wm * 32 + mi * 16 + group + ((c & 2) ? 8 : 0);
                const int n = n0 + wn * 32 + nj * 8 + tig * 2 + (c & 1);
                float v = fmaxf(drive[n] * (1.0f + sigmoidf(acc[mi][nj][c])) - ca1bias[n], 0.0f);
                const int gi = m * NDIM + n;
                if (last) ca1[gi] = v;
                g_at2[gi] = tf32r(v);
                if (m == 0) c1h[t * NDIM + n] = v;
            }
}

// ---------------------------------------------------------------------------
// step2: ec5 += ca1 @ wca1ec5; squash; ec3 *= ec5; cue @ t==10; threefry noise
// ---------------------------------------------------------------------------
__global__ __launch_bounds__(256) void step2_mma(
    const int* __restrict__ cue,
    float* __restrict__ ec3, float* __restrict__ ec5,
    float* __restrict__ e3h, float* __restrict__ e5h, int t)
{
    extern __shared__ float sm[];
    float acc[2][4][4];
    gemm_mma_tf32(g_at2, g_wt2, sm, acc);

    const int lane = threadIdx.x & 31, warp = threadIdx.x >> 5;
    const int group = lane >> 2, tig = lane & 3;
    const int wm = warp & 3, wn = warp >> 2;
    const int m0 = blockIdx.y * 128, n0 = blockIdx.x * 64;
    const uint32_t k0 = g_keys[2 * t], k1 = g_keys[2 * t + 1];
    const bool at_cue = (t == 10);

#pragma unroll
    for (int mi = 0; mi < 2; mi++)
#pragma unroll
        for (int nj = 0; nj < 4; nj++)
#pragma unroll
            for (int c = 0; c < 4; c++) {
                const int m = m0 + wm * 32 + mi * 16 + group + ((c & 2) ? 8 : 0);
                const int n = n0 + wn * 32 + nj * 8 + tig * 2 + (c & 1);
                const int gi = m * NDIM + n;
                float e5 = ec5[gi] + acc[mi][nj][c];       // 10*TS == 1.0 exactly
                e5 = 0.69f + 0.3f * sigmoidf(4.0f * (e5 - 0.3f));
                float e3 = e5 * ec3[gi];
                if (at_cue && (cue[gi] != 0)) e3 = 0.4f * e3 + 0.6f;
                if (noise_hit(k0, k1, (uint32_t)gi)) e3 = 0.5f * e3 + 0.3f;
                ec5[gi] = e5;
                ec3[gi] = e3;
                g_at1[gi] = tf32r(e3);
                if (m == 0) { e5h[t * NDIM + n] = e5; e3h[t * NDIM + n] = e3; }
            }
}

// ---------------------------------------------------------------------------
// act_cell = ca1 @ wca1act + actbias (tf32 operands, validated)
// ---------------------------------------------------------------------------
__global__ __launch_bounds__(128) void act_kernel(
    const float* __restrict__ ca1, const float* __restrict__ w,
    const float* __restrict__ bias, float* __restrict__ out)
{
    __shared__ float s0[128], s1[128];
    const int b = blockIdx.x;
    float a0 = 0.0f, a1 = 0.0f;
    for (int c = threadIdx.x; c < NDIM; c += 128) {
        float v = tf32r(ca1[b * NDIM + c]);
        a0 += v * tf32r(w[c * 2 + 0]);
        a1 += v * tf32r(w[c * 2 + 1]);
    }
    s0[threadIdx.x] = a0; s1[threadIdx.x] = a1;
    __syncthreads();
    for (int off = 64; off > 0; off >>= 1) {
        if (threadIdx.x < off) {
            s0[threadIdx.x] += s0[threadIdx.x + off];
            s1[threadIdx.x] += s1[threadIdx.x + off];
        }
        __syncthreads();
    }
    if (threadIdx.x == 0) {
        out[b * 2 + 0] = s0[0] + bias[0];
        out[b * 2 + 1] = s1[0] + bias[1];
    }
}

// ---------------------------------------------------------------------------
extern "C" void kernel_launch(void* const* d_in, const int* in_sizes, int n_in,
                              void* d_out, int out_size) {
    const int*   cue      = (const int*)d_in[0];     // bool -> int32 in harness
    const float* ec3_last = (const float*)d_in[1];
    const float* ec5_last = (const float*)d_in[2];
    const float* ca1_last = (const float*)d_in[3];
    const float* ca1bias  = (const float*)d_in[4];
    const float* wca3ca1  = (const float*)d_in[5];
    const float* wec3ca1  = (const float*)d_in[6];
    const float* wca1ec5  = (const float*)d_in[7];
    const float* wca1act  = (const float*)d_in[8];
    const float* actbias  = (const float*)d_in[9];
    (void)ca1_last;

    float* out = (float*)d_out;
    float* act = out + OFF_ACT;
    float* e3h = out + OFF_E3H;
    float* e5h = out + OFF_E5H;
    float* c1h = out + OFF_C1H;
    float* ec3 = out + OFF_EC3;
    float* ec5 = out + OFF_EC5;
    float* ca1 = out + OFF_CA1;

    cudaFuncSetAttribute(step1_mma, cudaFuncAttributeMaxDynamicSharedMemorySize, SMEM_DYN);
    cudaFuncSetAttribute(step2_mma, cudaFuncAttributeMaxDynamicSharedMemorySize, SMEM_DYN);

    // single prologue launch (transposes, state init, drive, keys)
    prep_kernel<<<4197, 256>>>(wec3ca1, wca1ec5, ec3_last, ec5_last, wca3ca1, ec3, ec5);

    dim3 grid(NDIM / 64, BSZ / 128);
    for (int t = 0; t < TLEN; t++) {
        step1_mma<<<grid, 256, SMEM_DYN>>>(ca1bias, ca1, c1h, t, t == TLEN - 1);
        step2_mma<<<grid, 256, SMEM_DYN>>>(cue, ec3, ec5, e3h, e5h, t);
    }
    act_kernel<<<BSZ, 128>>>(ca1, wca1act, actbias, act);
}